// round 14
// baseline (speedup 1.0000x reference)
#include <cuda_runtime.h>
#include <cuda_fp16.h>
#include <math.h>
#include <stdint.h>

#define B_ 4
#define C_ 192
#define H_ 192
#define W_ 192
#define HW_ (H_*W_)
#define HEADS 6
#define PW 194
#define KTOT 192
#define NT 192

// ------------------ scratch ------------------
__device__ __align__(128) __half g_xh[(size_t)B_*PW*PW*C_];
__device__ __align__(128) __half g_yh[(size_t)B_*HW_*C_],   g_yl[(size_t)B_*HW_*C_];
__device__ __align__(128) __half g_vh[(size_t)B_*HW_*C_],   g_vl[(size_t)B_*HW_*C_];
__device__ __align__(128) __half g_kraw[(size_t)B_*C_*HW_]; // k after 1x1, fp16
__device__ __align__(128) __half g_kd  [(size_t)B_*C_*HW_]; // k after dwconv, fp16
__device__ __align__(128) __half g_q16 [(size_t)B_*C_*HW_]; // q conv out, fp16
__device__ __align__(128) float  g_vraw[(size_t)B_*C_*HW_]; // v after 1x1, fp32
__device__ __align__(128) float  g_vd  [(size_t)B_*C_*HW_]; // v after dwconv, fp32
__device__ __align__(128) __half g_kvwh[384*192], g_kvwl[384*192];
__device__ __align__(128) __half g_qwh[192*9*192];
__device__ __align__(128) __half g_wfh[B_*192*192], g_wfl[B_*192*192];
__device__ __align__(128) float  g_gram[B_*HEADS*32*32];
__device__ __align__(128) float  g_qss[B_*C_], g_kss[B_*C_];
__device__ __align__(128) float  g_weff[(size_t)B_*C_*C_];

// ------------------ PTX helpers (baseline features only) ------------------
__device__ __forceinline__ uint32_t s2u(const void* p){
    uint32_t a;
    asm("{ .reg .u64 t; cvta.to.shared.u64 t, %1; cvt.u32.u64 %0, t; }":"=r"(a):"l"(p));
    return a;
}
#define SWZ(o) ((o) ^ (((o)>>3)&0x70))
__device__ __forceinline__ void cpa16(uint32_t d, const void* s){
    asm volatile("cp.async.cg.shared.global [%0], [%1], 16;"::"r"(d),"l"(s));
}
__device__ __forceinline__ void ldsm4(uint32_t* r, uint32_t a){
    asm volatile("ldmatrix.sync.aligned.m8n8.x4.shared.b16 {%0,%1,%2,%3}, [%4];"
        :"=r"(r[0]),"=r"(r[1]),"=r"(r[2]),"=r"(r[3]):"r"(a));
}
__device__ __forceinline__ void ldsm2(uint32_t* r, uint32_t a){
    asm volatile("ldmatrix.sync.aligned.m8n8.x2.shared.b16 {%0,%1}, [%2];"
        :"=r"(r[0]),"=r"(r[1]):"r"(a));
}
__device__ __forceinline__ void mma16816(float* c, const uint32_t* a, const uint32_t* b){
    asm volatile("mma.sync.aligned.m16n8k16.row.col.f32.f16.f16.f32 "
        "{%0,%1,%2,%3}, {%4,%5,%6,%7}, {%8,%9}, {%0,%1,%2,%3};"
        : "+f"(c[0]),"+f"(c[1]),"+f"(c[2]),"+f"(c[3])
        : "r"(a[0]),"r"(a[1]),"r"(a[2]),"r"(a[3]),"r"(b[0]),"r"(b[1]));
}

// ------------------ prepack kernels ------------------
__device__ __forceinline__ void split_h(float v, __half& h, __half& l){
    h = __float2half_rn(v);
    l = __float2half_rn(v - __half2float(h));
}

// fp32 [C][HW] -> fp16 hi/lo [HW][C] (pixel-major)
__global__ void t32(const float* __restrict__ src, size_t sBatch,
                    __half* __restrict__ dh, __half* __restrict__ dl)
{
    __shared__ float t[32][33];
    int p0 = blockIdx.x*32, c0 = blockIdx.y*32, b = blockIdx.z;
    const float* s = src + (size_t)b*sBatch;
    int tx = threadIdx.x, ty = threadIdx.y;
    #pragma unroll
    for (int j=0;j<4;j++)
        t[ty+8*j][tx] = s[(size_t)(c0+ty+8*j)*HW_ + p0+tx];
    __syncthreads();
    #pragma unroll
    for (int j=0;j<4;j++){
        __half hh,ll; split_h(t[tx][ty+8*j], hh, ll);
        size_t o = ((size_t)b*HW_ + p0+ty+8*j)*C_ + c0+tx;
        dh[o]=hh; dl[o]=ll;
    }
}

// fp32 x [C][HW] -> padded fp16 (hi only) [194][194][C]
__global__ void t32pad(const float* __restrict__ src, __half* __restrict__ dh)
{
    __shared__ float t[32][33];
    int p0 = blockIdx.x*32, c0 = blockIdx.y*32, b = blockIdx.z;
    const float* s = src + (size_t)b*C_*HW_;
    int tx = threadIdx.x, ty = threadIdx.y;
    #pragma unroll
    for (int j=0;j<4;j++)
        t[ty+8*j][tx] = s[(size_t)(c0+ty+8*j)*HW_ + p0+tx];
    __syncthreads();
    #pragma unroll
    for (int j=0;j<4;j++){
        int p = p0+ty+8*j, yy = p/W_, xx = p%W_;
        size_t o = ((size_t)b*PW*PW + (size_t)(yy+1)*PW + (xx+1))*C_ + c0+tx;
        dh[o] = __float2half_rn(t[tx][ty+8*j]);
    }
}

__global__ void zb(__half* __restrict__ dh)
{
    int i = blockIdx.x*256 + threadIdx.x;
    const int per_b = 772*C_;
    if (i >= B_*per_b) return;
    int b = i/per_b, rem = i%per_b, ridx = rem/C_, c = rem%C_;
    int yy, xx;
    if (ridx < 194)      { yy=0;   xx=ridx; }
    else if (ridx < 388) { yy=193; xx=ridx-194; }
    else if (ridx < 580) { yy=ridx-388+1; xx=0; }
    else                 { yy=ridx-580+1; xx=193; }
    size_t o = ((size_t)b*PW*PW + (size_t)yy*PW + xx)*C_ + c;
    dh[o] = __float2half_rn(0.f);
}

__global__ void pack_kvw(const float* __restrict__ w,
                         __half* __restrict__ h, __half* __restrict__ l)
{
    int i = blockIdx.x*256 + threadIdx.x;
    if (i >= 384*192) return;
    __half hh,ll; split_h(w[i], hh, ll); h[i]=hh; l[i]=ll;
}

// q_w [192][192][3][3] -> [192][9][192] (hi only)
__global__ void pack_qw(const float* __restrict__ w, __half* __restrict__ h)
{
    int i = blockIdx.x*256 + threadIdx.x;
    if (i >= 192*9*192) return;
    int oc = i/(9*192), rem = i%(9*192), t = rem/192, ic = rem%192;
    h[i] = __float2half_rn(w[((size_t)(oc*192+ic))*9 + t]);
}

__global__ void pack_weff(__half* __restrict__ h, __half* __restrict__ l)
{
    int i = blockIdx.x*256 + threadIdx.x;
    if (i >= B_*192*192) return;
    __half hh,ll; split_h(g_weff[i], hh, ll); h[i]=hh; l[i]=ll;
}

// ------------------ hgemm: 192x192 tile, 384 thr (12 warps 3m x 4n) ----------
// Y[b] = A[b](192x192) @ B[b](pixel-major [HW][192])^T, K=192 in 3 chunks.
// TERMS=3: hi/lo split. OUTH=1: write fp16.
template<int TERMS, int OUTH>
__global__ __launch_bounds__(384,1) void hgemm(
    const __half* __restrict__ Ah, const __half* __restrict__ Al, size_t aBatch,
    const __half* __restrict__ Bh, const __half* __restrict__ Bl,
    void* __restrict__ out, size_t oBatch)
{
    constexpr uint32_t ASZ  = 192u*128u;
    constexpr uint32_t BOFF = (TERMS==3 ? 2u : 1u)*ASZ;
    constexpr uint32_t STG  = BOFF + (TERMS==3 ? 2u : 1u)*24576u;
    extern __shared__ char smem[];
    uint32_t sb = s2u(smem);
    int tid = threadIdx.x, lane = tid&31, wid = tid>>5;
    int wm = wid>>2, wn = wid&3;
    int bx = blockIdx.x, b = blockIdx.y;
    const __half* Ahb = Ah + (size_t)b*aBatch;
    const __half* Alb = (TERMS==3) ? Al + (size_t)b*aBatch : nullptr;
    const __half* Bhb = Bh + (size_t)b*HW_*C_ + (size_t)bx*NT*C_;
    const __half* Blb = (TERMS==3) ? Bl + (size_t)b*HW_*C_ + (size_t)bx*NT*C_ : nullptr;

    auto load = [&](int kc){
        uint32_t base = sb + (uint32_t)(kc&1)*STG;
        #pragma unroll
        for (int i=0;i<4;i++){
            int idx = tid + i*384; int r = idx>>3, j = idx&7;
            size_t ge = (size_t)r*KTOT + kc*64;
            uint32_t off = SWZ((uint32_t)(r*128 + j*16));
            cpa16(base + 0u + off, (const char*)(Ahb+ge) + j*16);
            if (TERMS==3) cpa16(base + ASZ + off, (const char*)(Alb+ge) + j*16);
        }
        #pragma unroll
        for (int i=0;i<4;i++){
            int idx = tid + i*384; int r = idx>>3, j = idx&7;
            size_t ge = (size_t)r*KTOT + kc*64;
            uint32_t off = SWZ((uint32_t)(r*128 + j*16));
            cpa16(base + BOFF + off, (const char*)(Bhb+ge) + j*16);
            if (TERMS==3) cpa16(base + BOFF + 24576u + off, (const char*)(Blb+ge) + j*16);
        }
        asm volatile("cp.async.commit_group;":::"memory");
    };

    float acc[4][6][4] = {};
    load(0);
    #pragma unroll 1
    for (int kc=0; kc<3; kc++){
        if (kc+1 < 3){
            load(kc+1);
            asm volatile("cp.async.wait_group 1;":::"memory");
        } else {
            asm volatile("cp.async.wait_group 0;":::"memory");
        }
        __syncthreads();
        uint32_t base = sb + (uint32_t)(kc&1)*STG;
        #pragma unroll
        for (int kk=0;kk<4;kk++){
            uint32_t ah[4][4], al[4][4], bh[6][2], bl[6][2];
            #pragma unroll
            for (int mt=0;mt<4;mt++){
                int row = wm*64 + mt*16 + (lane&15);
                uint32_t off = SWZ((uint32_t)(row*128 + (2*kk + (lane>>4))*16));
                ldsm4(ah[mt], base + 0u + off);
                if (TERMS==3) ldsm4(al[mt], base + ASZ + off);
            }
            #pragma unroll
            for (int nt=0;nt<6;nt++){
                int rn = wn*48 + nt*8 + (lane&7);
                uint32_t off = SWZ((uint32_t)(rn*128 + (2*kk + ((lane>>3)&1))*16));
                ldsm2(bh[nt], base + BOFF + off);
                if (TERMS==3) ldsm2(bl[nt], base + BOFF + 24576u + off);
            }
            #pragma unroll
            for (int mt=0;mt<4;mt++)
                #pragma unroll
                for (int nt=0;nt<6;nt++){
                    mma16816(acc[mt][nt], ah[mt], bh[nt]);
                    if (TERMS==3){
                        mma16816(acc[mt][nt], ah[mt], bl[nt]);
                        mma16816(acc[mt][nt], al[mt], bh[nt]);
                    }
                }
        }
        __syncthreads();
    }

    #pragma unroll
    for (int mt=0;mt<4;mt++){
        int row = wm*64 + mt*16 + (lane>>2);
        #pragma unroll
        for (int nt=0;nt<6;nt++){
            int col = bx*NT + wn*48 + nt*8 + (lane&3)*2;
            if (OUTH){
                __half* o = (__half*)out + (size_t)b*oBatch;
                *(__half2*)(o + (size_t)row*HW_ + col)
                    = __floats2half2_rn(acc[mt][nt][0], acc[mt][nt][1]);
                *(__half2*)(o + (size_t)(row+8)*HW_ + col)
                    = __floats2half2_rn(acc[mt][nt][2], acc[mt][nt][3]);
            } else {
                float* o = (float*)out + (size_t)b*oBatch;
                *(float2*)(o + (size_t)row*HW_ + col)
                    = make_float2(acc[mt][nt][0], acc[mt][nt][1]);
                *(float2*)(o + (size_t)(row+8)*HW_ + col)
                    = make_float2(acc[mt][nt][2], acc[mt][nt][3]);
            }
        }
    }
}

// ------------------ hconv: conv3x3, image rows loaded ONCE per kc -------------
// SMEM: A dbl-buf 2x24576 @0; B dbl-buf 2x(3 rows x 194px x 128B = 74496) @49152.
// it = kc*9 + tap; tap (ky,kx) reads row-buffer ky at row index rn+kx.
__global__ __launch_bounds__(384,1) void hconv(
    const __half* __restrict__ Wq, const __half* __restrict__ X,
    __half* __restrict__ out)
{
    constexpr uint32_t BB0 = 49152u, BROW = 24832u, BSTG = 3u*BROW;
    extern __shared__ char smem[];
    uint32_t sb = s2u(smem);
    int tid = threadIdx.x, lane = tid&31, wid = tid>>5;
    int wm = wid>>2, wn = wid&3;
    int yrow = blockIdx.x, b = blockIdx.y;
    const __half* Xb = X + (size_t)b*PW*PW*C_;

    auto loadA = [&](int it){
        int tap = it%9, kc = it/9;
        uint32_t base = sb + (uint32_t)(it&1)*24576u;
        #pragma unroll
        for (int i=0;i<4;i++){
            int idx = tid + i*384; int r = idx>>3, j = idx&7;
            size_t ge = ((size_t)r*9 + tap)*KTOT + kc*64;
            cpa16(base + SWZ((uint32_t)(r*128 + j*16)), (const char*)(Wq+ge) + j*16);
        }
    };
    auto loadB = [&](int kc){
        uint32_t base = sb + BB0 + (uint32_t)(kc&1)*BSTG;
        for (int l = tid; l < 3*194*8; l += 384){
            int j = l&7; int p = (l>>3)%194; int ky = (l>>3)/194;
            size_t ge = ((size_t)(yrow+ky)*PW + p)*C_ + kc*64;
            cpa16(base + (uint32_t)ky*BROW + SWZ((uint32_t)(p*128 + j*16)),
                  (const char*)(Xb+ge) + j*16);
        }
    };

    float acc[4][6][4] = {};
    loadB(0); loadA(0);
    asm volatile("cp.async.commit_group;":::"memory");
    #pragma unroll 1
    for (int it=0; it<27; it++){
        int tap = it%9, kc = it/9;
        if (it+1 < 27){
            loadA(it+1);
            if (tap==8) loadB(kc+1);
            asm volatile("cp.async.commit_group;":::"memory");
            asm volatile("cp.async.wait_group 1;":::"memory");
        } else {
            asm volatile("cp.async.wait_group 0;":::"memory");
        }
        __syncthreads();
        int ky = tap/3, kx = tap%3;
        uint32_t abase = sb + (uint32_t)(it&1)*24576u;
        uint32_t bbase = sb + BB0 + (uint32_t)(kc&1)*BSTG + (uint32_t)ky*BROW;
        #pragma unroll
        for (int kk=0;kk<4;kk++){
            uint32_t ah[4][4], bh[6][2];
            #pragma unroll
            for (int mt=0;mt<4;mt++){
                int row = wm*64 + mt*16 + (lane&15);
                ldsm4(ah[mt], abase + SWZ((uint32_t)(row*128 + (2*kk + (lane>>4))*16)));
            }
            #pragma unroll
            for (int nt=0;nt<6;nt++){
                int rn = wn*48 + nt*8 + (lane&7) + kx;
                ldsm2(bh[nt], bbase + SWZ((uint32_t)(rn*128 + (2*kk + ((lane>>3)&1))*16)));
            }
            #pragma unroll
            for (int mt=0;mt<4;mt++)
                #pragma unroll
                for (int nt=0;nt<6;nt++)
                    mma16816(acc[mt][nt], ah[mt], bh[nt]);
        }
        __syncthreads();
    }

    __half* ob = out + (size_t)b*C_*HW_ + (size_t)yrow*W_;
    #pragma unroll
    for (int mt=0;mt<4;mt++){
        int row = wm*64 + mt*16 + (lane>>2);
        #pragma unroll
        for (int nt=0;nt<6;nt++){
            int col = wn*48 + nt*8 + (lane&3)*2;
            *(__half2*)(ob + (size_t)row*HW_ + col)
                = __floats2half2_rn(acc[mt][nt][0], acc[mt][nt][1]);
            *(__half2*)(ob + (size_t)(row+8)*HW_ + col)
                = __floats2half2_rn(acc[mt][nt][2], acc[mt][nt][3]);
        }
    }
}

// ------------------ depthwise 3x3, smem-tiled, templated dtype ---------------
template<typename T>
__global__ __launch_bounds__(256) void dwconv_t(const T* __restrict__ in,
                                                const float* __restrict__ w,
                                                T* __restrict__ out)
{
    __shared__ float s[34][196];
    int y0 = blockIdx.x*32;
    int ch = blockIdx.y;
    int b  = blockIdx.z;
    int tid = threadIdx.x;
    const T* src = in + ((size_t)b*C_ + ch)*HW_;
    for (int l = tid; l < 34*194; l += 256){
        int r = l/194, c = l%194;
        int gy = y0 + r - 1, gx = c - 1;
        float v = 0.f;
        if ((unsigned)gy < (unsigned)H_ && (unsigned)gx < (unsigned)W_)
            v = (float)src[(size_t)gy*W_ + gx];
        s[r][c] = v;
    }
    float w0=w[ch*9+0], w1=w[ch*9+1], w2=w[ch*9+2],
          w3=w[ch*9+3], w4=w[ch*9+4], w5=w[ch*9+5],
          w6=w[ch*9+6], w7=w[ch*9+7], w8=w[ch*9+8];
    __syncthreads();
    T* dst = out + ((size_t)b*C_ + ch)*HW_ + (size_t)y0*W_;
    for (int l = tid; l < 32*192; l += 256){
        int r = l/192, c = l%192;
        float acc = w0*s[r  ][c] + w1*s[r  ][c+1] + w2*s[r  ][c+2]
                  + w3*s[r+1][c] + w4*s[r+1][c+1] + w5*s[r+1][c+2]
                  + w6*s[r+2][c] + w7*s[r+2][c+1] + w8*s[r+2][c+2];
        dst[(size_t)r*W_ + c] = (T)acc;
    }
}

// ------------------ gram (+fused norms), softmax, fold ------------------
__global__ void zero_acc()
{
    int i = blockIdx.x * 256 + threadIdx.x;
    if (i < B_*HEADS*32*32) g_gram[i] = 0.f;
    else if (i < B_*HEADS*32*32 + B_*C_) g_qss[i - B_*HEADS*32*32] = 0.f;
    else if (i < B_*HEADS*32*32 + 2*B_*C_) g_kss[i - B_*HEADS*32*32 - B_*C_] = 0.f;
}

__global__ __launch_bounds__(256) void gram_kernel(const __half* __restrict__ q,
                                                   const __half* __restrict__ kk)
{
    int split = blockIdx.x;
    int bh = blockIdx.y;
    int b = bh / HEADS, h = bh % HEADS;
    __shared__ float qs[32][65], ks[32][65];
    const __half* qb = q  + ((size_t)b*C_ + h*32)*HW_;
    const __half* kb = kk + ((size_t)b*C_ + h*32)*HW_;
    int n0 = split * (HW_/8);
    int tid = threadIdx.x;
    int c = tid >> 3, d0 = (tid & 7) << 2;
    int sub = tid & 7;
    float acc[4] = {0.f, 0.f, 0.f, 0.f};
    float ssq = 0.f;
    for (int nt = 0; nt < HW_/8; nt += 64) {
        for (int l = tid; l < 2048; l += 256) {
            int cc = l >> 6, nn = l & 63;
            size_t off = (size_t)cc*HW_ + n0 + nt + nn;
            qs[cc][nn] = __half2float(qb[off]);
            ks[cc][nn] = __half2float(kb[off]);
        }
        __syncthreads();
        #pragma unroll 8
        for (int n = 0; n < 64; n++) {
            float qv = qs[c][n];
            #pragma unroll
            for (int j = 0; j < 4; j++) acc[j] += qv * ks[d0+j][n];
        }
        if (sub == 0) {
            #pragma unroll 8
            for (int n = 0; n < 64; n++) { float v = qs[c][n]; ssq += v*v; }
        } else if (sub == 1) {
            #pragma unroll 8
            for (int n = 0; n < 64; n++) { float v = ks[c][n]; ssq += v*v; }
        }
        __syncthreads();
    }
    #pragma unroll
    for (int j = 0; j < 4; j++)
        atomicAdd(&g_gram[((size_t)bh*32 + c)*32 + d0 + j], acc[j]);
    if (sub == 0) atomicAdd(&g_qss[b*C_ + h*32 + c], ssq);
    else if (sub == 1) atomicAdd(&g_kss[b*C_ + h*32 + c], ssq);
}

__global__ __launch_bounds__(256) void softfold(const float* __restrict__ temp,
                                                const float* __restrict__ proj)
{
    int bh = blockIdx.x;
    int b = bh / HEADS, h = bh % HEADS;
    __shared__ float attn[32][33];
    __shared__ float iq[32], ik[32];
    int tid = threadIdx.x;
    int wrp = tid >> 5, ln = tid & 31;
    if (tid < 32)
        iq[tid] = 1.f / fmaxf(sqrtf(g_qss[b*C_ + h*32 + tid]), 1e-12f);
    else if (tid < 64)
        ik[tid-32] = 1.f / fmaxf(sqrtf(g_kss[b*C_ + h*32 + tid-32]), 1e-12f);
    __syncthreads();
    float tmp = temp[h];
    for (int r = wrp; r < 32; r += 8) {
        float v = g_gram[((size_t)bh*32 + r)*32 + ln] * iq[r] * ik[ln] * tmp;
        float m = v;
        #pragma unroll
        for (int off = 16; off; off >>= 1) m = fmaxf(m, __shfl_xor_sync(0xffffffff, m, off));
        float e = expf(v - m);
        float s = e;
        #pragma unroll
        for (int off = 16; off; off >>= 1) s += __shfl_xor_sync(0xffffffff, s, off);
        attn[r][ln] = e / s;
    }
    __syncthreads();
    for (int l = tid; l < C_*32; l += 256) {
        int co = l >> 5, d = l & 31;
        float s = 0.f;
        #pragma unroll
        for (int cc = 0; cc < 32; cc++)
            s += proj[(size_t)co*C_ + h*32 + cc] * attn[cc][d];
        g_weff[((size_t)b*C_ + co)*C_ + h*32 + d] = s;
    }
}

// ------------------ launcher ------------------
extern "C" void kernel_launch(void* const* d_in, const int* in_sizes, int n_in,
                              void* d_out, int out_size)
{
    const float* x           = (const float*)d_in[0];
    const float* y           = (const float*)d_in[1];
    const float* q_w         = (const float*)d_in[2];
    const float* kv_w        = (const float*)d_in[3];
    const float* kvdw_w      = (const float*)d_in[4];
    const float* proj_w      = (const float*)d_in[5];
    const float* temperature = (const float*)d_in[6];

    float *p_vraw, *p_vd;
    __half *p_xh,*p_yh,*p_yl,*p_vh,*p_vl,*p_kraw,*p_kd,*p_q16;
    __half *p_kvwh,*p_kvwl,*p_qwh,*p_wfh,*p_wfl;
    cudaGetSymbolAddress((void**)&p_vraw, g_vraw); cudaGetSymbolAddress((void**)&p_vd, g_vd);
    cudaGetSymbolAddress((void**)&p_kraw, g_kraw); cudaGetSymbolAddress((void**)&p_kd, g_kd);
    cudaGetSymbolAddress((void**)&p_q16, g_q16);
    cudaGetSymbolAddress((void**)&p_xh, g_xh);
    cudaGetSymbolAddress((void**)&p_yh, g_yh);   cudaGetSymbolAddress((void**)&p_yl, g_yl);
    cudaGetSymbolAddress((void**)&p_vh, g_vh);   cudaGetSymbolAddress((void**)&p_vl, g_vl);
    cudaGetSymbolAddress((void**)&p_kvwh, g_kvwh); cudaGetSymbolAddress((void**)&p_kvwl, g_kvwl);
    cudaGetSymbolAddress((void**)&p_qwh, g_qwh);
    cudaGetSymbolAddress((void**)&p_wfh, g_wfh); cudaGetSymbolAddress((void**)&p_wfl, g_wfl);

    const int SM_T1 = 98304, SM_T3 = 196608, SM_CV = 49152 + 2*74496;
    cudaFuncSetAttribute(hgemm<1,1>, cudaFuncAttributeMaxDynamicSharedMemorySize, SM_T1);
    cudaFuncSetAttribute(hgemm<3,0>, cudaFuncAttributeMaxDynamicSharedMemorySize, SM_T3);
    cudaFuncSetAttribute(hconv, cudaFuncAttributeMaxDynamicSharedMemorySize, SM_CV);

    dim3 tb(32,8);
    // prepack
    pack_kvw<<<(384*192+255)/256, 256>>>(kv_w, p_kvwh, p_kvwl);
    pack_qw <<<(192*9*192+255)/256, 256>>>(q_w, p_qwh);
    t32pad<<<dim3(HW_/32, C_/32, B_), tb>>>(x, p_xh);
    zb<<<(B_*772*C_+255)/256, 256>>>(p_xh);
    t32<<<dim3(HW_/32, C_/32, B_), tb>>>(y, (size_t)C_*HW_, p_yh, p_yl);

    // k = kv_w[0:192] @ y   (1-term, fp16 out — attenuated path)
    hgemm<1,1><<<dim3(HW_/NT, B_), 384, SM_T1>>>(
        p_kvwh, nullptr, 0, p_yh, nullptr, p_kraw, (size_t)C_*HW_);

    // v = kv_w[192:384] @ y (3-term, fp32 out — output linear in v)
    hgemm<3,0><<<dim3(HW_/NT, B_), 384, SM_T3>>>(
        p_kvwh + (size_t)192*192, p_kvwl + (size_t)192*192, 0,
        p_yh, p_yl, p_vraw, (size_t)C_*HW_);

    // depthwise 3x3 (k fp16, v fp32)
    dwconv_t<__half><<<dim3(H_/32, C_, B_), 256>>>(p_kraw, kvdw_w, p_kd);
    dwconv_t<float ><<<dim3(H_/32, C_, B_), 256>>>(p_vraw, kvdw_w + 192*9, p_vd);

    // q = conv3x3(x): image rows loaded once per kc, 9 shifted-window taps
    hconv<<<dim3(H_, B_), 384, SM_CV>>>(p_qwh, p_xh, p_q16);

    // v -> pixel-major fp16 hi/lo
    t32<<<dim3(HW_/32, C_/32, B_), tb>>>(p_vd, (size_t)C_*HW_, p_vh, p_vl);

    // gram (+fused norms), softmax, fold proj
    zero_acc<<<(B_*HEADS*32*32 + 2*B_*C_ + 255)/256, 256>>>();
    gram_kernel<<<dim3(8, B_*HEADS), 256>>>(p_q16, p_kd);
    softfold<<<B_*HEADS, 256>>>(temperature, proj_w);
    pack_weff<<<(B_*192*192+255)/256, 256>>>(p_wfh, p_wfl);

    // out = W_eff[b](192x192) @ v[b]  (3-term, fp32 out)
    hgemm<3,0><<<dim3(HW_/NT, B_), 384, SM_T3>>>(
        p_wfh, p_wfl, (size_t)192*192, p_vh, p_vl, d_out, (size_t)C_*HW_);
}

// round 16
// speedup vs baseline: 1.0132x; 1.0132x over previous
#include <cuda_runtime.h>
#include <cuda_fp16.h>
#include <math.h>
#include <stdint.h>

#define B_ 4
#define C_ 192
#define H_ 192
#define W_ 192
#define HW_ (H_*W_)
#define HEADS 6
#define PW 194
#define KTOT 192
#define NT 192

// ------------------ scratch ------------------
__device__ __align__(128) __half g_xh[(size_t)B_*PW*PW*C_];
__device__ __align__(128) __half g_yh[(size_t)B_*HW_*C_],   g_yl[(size_t)B_*HW_*C_];
__device__ __align__(128) __half g_vh[(size_t)B_*HW_*C_],   g_vl[(size_t)B_*HW_*C_];
__device__ __align__(128) __half g_kraw[(size_t)B_*C_*HW_]; // k after 1x1, fp16
__device__ __align__(128) __half g_kd  [(size_t)B_*C_*HW_]; // k after dwconv, fp16
__device__ __align__(128) __half g_q16 [(size_t)B_*C_*HW_]; // q conv out, fp16
__device__ __align__(128) float  g_vraw[(size_t)B_*C_*HW_]; // v after 1x1, fp32
__device__ __align__(128) float  g_vd  [(size_t)B_*C_*HW_]; // v after dwconv, fp32
__device__ __align__(128) __half g_kvwh[384*192], g_kvwl[384*192];
__device__ __align__(128) __half g_qwh[192*9*192];
__device__ __align__(128) __half g_wfh[B_*192*192], g_wfl[B_*192*192];
__device__ __align__(128) float  g_gram[B_*HEADS*32*32];
__device__ __align__(128) float  g_qss[B_*C_], g_kss[B_*C_];
__device__ __align__(128) float  g_weff[(size_t)B_*C_*C_];

// ------------------ PTX helpers (baseline features only) ------------------
__device__ __forceinline__ uint32_t s2u(const void* p){
    uint32_t a;
    asm("{ .reg .u64 t; cvta.to.shared.u64 t, %1; cvt.u32.u64 %0, t; }":"=r"(a):"l"(p));
    return a;
}
#define SWZ(o) ((o) ^ (((o)>>3)&0x70))
__device__ __forceinline__ void cpa16(uint32_t d, const void* s){
    asm volatile("cp.async.cg.shared.global [%0], [%1], 16;"::"r"(d),"l"(s));
}
__device__ __forceinline__ void ldsm4(uint32_t* r, uint32_t a){
    asm volatile("ldmatrix.sync.aligned.m8n8.x4.shared.b16 {%0,%1,%2,%3}, [%4];"
        :"=r"(r[0]),"=r"(r[1]),"=r"(r[2]),"=r"(r[3]):"r"(a));
}
__device__ __forceinline__ void ldsm2(uint32_t* r, uint32_t a){
    asm volatile("ldmatrix.sync.aligned.m8n8.x2.shared.b16 {%0,%1}, [%2];"
        :"=r"(r[0]),"=r"(r[1]):"r"(a));
}
__device__ __forceinline__ void mma16816(float* c, const uint32_t* a, const uint32_t* b){
    asm volatile("mma.sync.aligned.m16n8k16.row.col.f32.f16.f16.f32 "
        "{%0,%1,%2,%3}, {%4,%5,%6,%7}, {%8,%9}, {%0,%1,%2,%3};"
        : "+f"(c[0]),"+f"(c[1]),"+f"(c[2]),"+f"(c[3])
        : "r"(a[0]),"r"(a[1]),"r"(a[2]),"r"(a[3]),"r"(b[0]),"r"(b[1]));
}

// ------------------ prepack kernels ------------------
__device__ __forceinline__ void split_h(float v, __half& h, __half& l){
    h = __float2half_rn(v);
    l = __float2half_rn(v - __half2float(h));
}

// fp32 [C][HW] -> fp16 hi/lo [HW][C] (pixel-major)
__global__ void t32(const float* __restrict__ src, size_t sBatch,
                    __half* __restrict__ dh, __half* __restrict__ dl)
{
    __shared__ float t[32][33];
    int p0 = blockIdx.x*32, c0 = blockIdx.y*32, b = blockIdx.z;
    const float* s = src + (size_t)b*sBatch;
    int tx = threadIdx.x, ty = threadIdx.y;
    #pragma unroll
    for (int j=0;j<4;j++)
        t[ty+8*j][tx] = s[(size_t)(c0+ty+8*j)*HW_ + p0+tx];
    __syncthreads();
    #pragma unroll
    for (int j=0;j<4;j++){
        __half hh,ll; split_h(t[tx][ty+8*j], hh, ll);
        size_t o = ((size_t)b*HW_ + p0+ty+8*j)*C_ + c0+tx;
        dh[o]=hh; dl[o]=ll;
    }
}

// fp32 x [C][HW] -> padded fp16 (hi only) [194][194][C]
__global__ void t32pad(const float* __restrict__ src, __half* __restrict__ dh)
{
    __shared__ float t[32][33];
    int p0 = blockIdx.x*32, c0 = blockIdx.y*32, b = blockIdx.z;
    const float* s = src + (size_t)b*C_*HW_;
    int tx = threadIdx.x, ty = threadIdx.y;
    #pragma unroll
    for (int j=0;j<4;j++)
        t[ty+8*j][tx] = s[(size_t)(c0+ty+8*j)*HW_ + p0+tx];
    __syncthreads();
    #pragma unroll
    for (int j=0;j<4;j++){
        int p = p0+ty+8*j, yy = p/W_, xx = p%W_;
        size_t o = ((size_t)b*PW*PW + (size_t)(yy+1)*PW + (xx+1))*C_ + c0+tx;
        dh[o] = __float2half_rn(t[tx][ty+8*j]);
    }
}

__global__ void zb(__half* __restrict__ dh)
{
    int i = blockIdx.x*256 + threadIdx.x;
    const int per_b = 772*C_;
    if (i >= B_*per_b) return;
    int b = i/per_b, rem = i%per_b, ridx = rem/C_, c = rem%C_;
    int yy, xx;
    if (ridx < 194)      { yy=0;   xx=ridx; }
    else if (ridx < 388) { yy=193; xx=ridx-194; }
    else if (ridx < 580) { yy=ridx-388+1; xx=0; }
    else                 { yy=ridx-580+1; xx=193; }
    size_t o = ((size_t)b*PW*PW + (size_t)yy*PW + xx)*C_ + c;
    dh[o] = __float2half_rn(0.f);
}

__global__ void pack_kvw(const float* __restrict__ w,
                         __half* __restrict__ h, __half* __restrict__ l)
{
    int i = blockIdx.x*256 + threadIdx.x;
    if (i >= 384*192) return;
    __half hh,ll; split_h(w[i], hh, ll); h[i]=hh; l[i]=ll;
}

// q_w [192][192][3][3] -> [192][9][192] (hi only)
__global__ void pack_qw(const float* __restrict__ w, __half* __restrict__ h)
{
    int i = blockIdx.x*256 + threadIdx.x;
    if (i >= 192*9*192) return;
    int oc = i/(9*192), rem = i%(9*192), t = rem/192, ic = rem%192;
    h[i] = __float2half_rn(w[((size_t)(oc*192+ic))*9 + t]);
}

__global__ void pack_weff(__half* __restrict__ h, __half* __restrict__ l)
{
    int i = blockIdx.x*256 + threadIdx.x;
    if (i >= B_*192*192) return;
    __half hh,ll; split_h(g_weff[i], hh, ll); h[i]=hh; l[i]=ll;
}

// ------------------ warp-MMA GEMM / conv: BM=192, 384 thr (12 warps 3m x 4n) --
// Y[b](192 x 192-tile) = sum_{tap,K} A[b] * B[b]^T.  M always exactly 192.
// TERMS=3: hi/lo split. TERMS=1: plain fp16. OUTH=1: fp16 output.
template<int TAPS, int TERMS, int OUTH>
__global__ __launch_bounds__(384,1) void hgemm(
    const __half* __restrict__ Ah, const __half* __restrict__ Al, size_t aBatch,
    const __half* __restrict__ Bh, const __half* __restrict__ Bl, size_t bBatch,
    size_t bRowStride, void* __restrict__ out, size_t oBatch)
{
    constexpr uint32_t ASZ  = 192u*128u;                    // 24576
    constexpr uint32_t BOFF = (TERMS==3 ? 2u : 1u)*ASZ;
    constexpr uint32_t STG  = BOFF + (TERMS==3 ? 2u : 1u)*24576u;
    extern __shared__ char smem[];
    uint32_t sb = s2u(smem);
    const int NC = 3*TAPS;
    int tid = threadIdx.x, lane = tid&31, wid = tid>>5;
    int wm = wid>>2, wn = wid&3;                            // 3 x 4
    int bx = blockIdx.x, b = blockIdx.y;
    const __half* Ahb = Ah + (size_t)b*aBatch;
    const __half* Alb = (TERMS==3) ? Al + (size_t)b*aBatch : nullptr;
    const __half* Bhb = Bh + (size_t)b*bBatch + (size_t)bx*bRowStride;
    const __half* Blb = (TERMS==3) ? Bl + (size_t)b*bBatch + (size_t)bx*bRowStride : nullptr;

    auto load = [&](int it){
        uint32_t base = sb + (uint32_t)(it&1)*STG;
        int tap = (TAPS==9)? it/3 : 0;
        int kc  = (TAPS==9)? it%3 : it;
        size_t tapOff = (TAPS==9)? (size_t)((tap/3)*PW + (tap%3))*C_ : 0;
        #pragma unroll
        for (int i=0;i<4;i++){                     // A: 192 rows x 8 x 16B
            int idx = tid + i*384; int r = idx>>3, j = idx&7;
            size_t ge = (size_t)r*((size_t)TAPS*KTOT) + (size_t)tap*KTOT + kc*64;
            uint32_t off = SWZ((uint32_t)(r*128 + j*16));
            cpa16(base + 0u + off, (const char*)(Ahb+ge) + j*16);
            if (TERMS==3) cpa16(base + ASZ + off, (const char*)(Alb+ge) + j*16);
        }
        #pragma unroll
        for (int i=0;i<4;i++){                     // B: 192 rows x 8 x 16B
            int idx = tid + i*384; int r = idx>>3, j = idx&7;
            size_t ge = tapOff + (size_t)r*KTOT + kc*64;
            uint32_t off = SWZ((uint32_t)(r*128 + j*16));
            cpa16(base + BOFF + off, (const char*)(Bhb+ge) + j*16);
            if (TERMS==3) cpa16(base + BOFF + 24576u + off, (const char*)(Blb+ge) + j*16);
        }
        asm volatile("cp.async.commit_group;":::"memory");
    };

    float acc[4][6][4] = {};

    load(0);
    #pragma unroll 1
    for (int it=0; it<NC; it++){
        if (it+1 < NC){
            load(it+1);
            asm volatile("cp.async.wait_group 1;":::"memory");
        } else {
            asm volatile("cp.async.wait_group 0;":::"memory");
        }
        __syncthreads();
        uint32_t base = sb + (uint32_t)(it&1)*STG;
        #pragma unroll
        for (int kk=0;kk<4;kk++){
            uint32_t ah[4][4], al[4][4], bh[6][2], bl[6][2];
            #pragma unroll
            for (int mt=0;mt<4;mt++){
                int row = wm*64 + mt*16 + (lane&15);
                uint32_t off = SWZ((uint32_t)(row*128 + (2*kk + (lane>>4))*16));
                ldsm4(ah[mt], base + 0u + off);
                if (TERMS==3) ldsm4(al[mt], base + ASZ + off);
            }
            #pragma unroll
            for (int nt=0;nt<6;nt++){
                int rn = wn*48 + nt*8 + (lane&7);
                uint32_t off = SWZ((uint32_t)(rn*128 + (2*kk + ((lane>>3)&1))*16));
                ldsm2(bh[nt], base + BOFF + off);
                if (TERMS==3) ldsm2(bl[nt], base + BOFF + 24576u + off);
            }
            #pragma unroll
            for (int mt=0;mt<4;mt++)
                #pragma unroll
                for (int nt=0;nt<6;nt++){
                    mma16816(acc[mt][nt], ah[mt], bh[nt]);
                    if (TERMS==3){
                        mma16816(acc[mt][nt], ah[mt], bl[nt]);
                        mma16816(acc[mt][nt], al[mt], bh[nt]);
                    }
                }
        }
        __syncthreads();
    }

    #pragma unroll
    for (int mt=0;mt<4;mt++){
        int row = wm*64 + mt*16 + (lane>>2);
        #pragma unroll
        for (int nt=0;nt<6;nt++){
            int col = bx*NT + wn*48 + nt*8 + (lane&3)*2;
            if (OUTH){
                __half* o = (__half*)out + (size_t)b*oBatch;
                *(__half2*)(o + (size_t)row*HW_ + col)
                    = __floats2half2_rn(acc[mt][nt][0], acc[mt][nt][1]);
                *(__half2*)(o + (size_t)(row+8)*HW_ + col)
                    = __floats2half2_rn(acc[mt][nt][2], acc[mt][nt][3]);
            } else {
                float* o = (float*)out + (size_t)b*oBatch;
                *(float2*)(o + (size_t)row*HW_ + col)
                    = make_float2(acc[mt][nt][0], acc[mt][nt][1]);
                *(float2*)(o + (size_t)(row+8)*HW_ + col)
                    = make_float2(acc[mt][nt][2], acc[mt][nt][3]);
            }
        }
    }
}

// ------------------ depthwise 3x3, smem-tiled, templated dtype ---------------
template<typename T>
__global__ __launch_bounds__(256) void dwconv_t(const T* __restrict__ in,
                                                const float* __restrict__ w,
                                                T* __restrict__ out)
{
    __shared__ float s[34][196];
    int y0 = blockIdx.x*32;
    int ch = blockIdx.y;
    int b  = blockIdx.z;
    int tid = threadIdx.x;
    const T* src = in + ((size_t)b*C_ + ch)*HW_;
    for (int l = tid; l < 34*194; l += 256){
        int r = l/194, c = l%194;
        int gy = y0 + r - 1, gx = c - 1;
        float v = 0.f;
        if ((unsigned)gy < (unsigned)H_ && (unsigned)gx < (unsigned)W_)
            v = (float)src[(size_t)gy*W_ + gx];
        s[r][c] = v;
    }
    float w0=w[ch*9+0], w1=w[ch*9+1], w2=w[ch*9+2],
          w3=w[ch*9+3], w4=w[ch*9+4], w5=w[ch*9+5],
          w6=w[ch*9+6], w7=w[ch*9+7], w8=w[ch*9+8];
    __syncthreads();
    T* dst = out + ((size_t)b*C_ + ch)*HW_ + (size_t)y0*W_;
    for (int l = tid; l < 32*192; l += 256){
        int r = l/192, c = l%192;
        float acc = w0*s[r  ][c] + w1*s[r  ][c+1] + w2*s[r  ][c+2]
                  + w3*s[r+1][c] + w4*s[r+1][c+1] + w5*s[r+1][c+2]
                  + w6*s[r+2][c] + w7*s[r+2][c+1] + w8*s[r+2][c+2];
        dst[(size_t)r*W_ + c] = (T)acc;
    }
}

// ------------------ gram (+fused norms), softmax, fold ------------------
__global__ void zero_acc()
{
    int i = blockIdx.x * 256 + threadIdx.x;
    if (i < B_*HEADS*32*32) g_gram[i] = 0.f;
    else if (i < B_*HEADS*32*32 + B_*C_) g_qss[i - B_*HEADS*32*32] = 0.f;
    else if (i < B_*HEADS*32*32 + 2*B_*C_) g_kss[i - B_*HEADS*32*32 - B_*C_] = 0.f;
}

__global__ __launch_bounds__(256) void gram_kernel(const __half* __restrict__ q,
                                                   const __half* __restrict__ kk)
{
    int split = blockIdx.x;
    int bh = blockIdx.y;
    int b = bh / HEADS, h = bh % HEADS;
    __shared__ float qs[32][65], ks[32][65];
    const __half* qb = q  + ((size_t)b*C_ + h*32)*HW_;
    const __half* kb = kk + ((size_t)b*C_ + h*32)*HW_;
    int n0 = split * (HW_/8);
    int tid = threadIdx.x;
    int c = tid >> 3, d0 = (tid & 7) << 2;
    int sub = tid & 7;
    float acc[4] = {0.f, 0.f, 0.f, 0.f};
    float ssq = 0.f;
    for (int nt = 0; nt < HW_/8; nt += 64) {
        for (int l = tid; l < 2048; l += 256) {
            int cc = l >> 6, nn = l & 63;
            size_t off = (size_t)cc*HW_ + n0 + nt + nn;
            qs[cc][nn] = __half2float(qb[off]);
            ks[cc][nn] = __half2float(kb[off]);
        }
        __syncthreads();
        #pragma unroll 8
        for (int n = 0; n < 64; n++) {
            float qv = qs[c][n];
            #pragma unroll
            for (int j = 0; j < 4; j++) acc[j] += qv * ks[d0+j][n];
        }
        if (sub == 0) {
            #pragma unroll 8
            for (int n = 0; n < 64; n++) { float v = qs[c][n]; ssq += v*v; }
        } else if (sub == 1) {
            #pragma unroll 8
            for (int n = 0; n < 64; n++) { float v = ks[c][n]; ssq += v*v; }
        }
        __syncthreads();
    }
    #pragma unroll
    for (int j = 0; j < 4; j++)
        atomicAdd(&g_gram[((size_t)bh*32 + c)*32 + d0 + j], acc[j]);
    if (sub == 0) atomicAdd(&g_qss[b*C_ + h*32 + c], ssq);
    else if (sub == 1) atomicAdd(&g_kss[b*C_ + h*32 + c], ssq);
}

__global__ __launch_bounds__(256) void softfold(const float* __restrict__ temp,
                                                const float* __restrict__ proj)
{
    int bh = blockIdx.x;
    int b = bh / HEADS, h = bh % HEADS;
    __shared__ float attn[32][33];
    __shared__ float iq[32], ik[32];
    int tid = threadIdx.x;
    int wrp = tid >> 5, ln = tid & 31;
    if (tid < 32)
        iq[tid] = 1.f / fmaxf(sqrtf(g_qss[b*C_ + h*32 + tid]), 1e-12f);
    else if (tid < 64)
        ik[tid-32] = 1.f / fmaxf(sqrtf(g_kss[b*C_ + h*32 + tid-32]), 1e-12f);
    __syncthreads();
    float tmp = temp[h];
    for (int r = wrp; r < 32; r += 8) {
        float v = g_gram[((size_t)bh*32 + r)*32 + ln] * iq[r] * ik[ln] * tmp;
        float m = v;
        #pragma unroll
        for (int off = 16; off; off >>= 1) m = fmaxf(m, __shfl_xor_sync(0xffffffff, m, off));
        float e = expf(v - m);
        float s = e;
        #pragma unroll
        for (int off = 16; off; off >>= 1) s += __shfl_xor_sync(0xffffffff, s, off);
        attn[r][ln] = e / s;
    }
    __syncthreads();
    for (int l = tid; l < C_*32; l += 256) {
        int co = l >> 5, d = l & 31;
        float s = 0.f;
        #pragma unroll
        for (int cc = 0; cc < 32; cc++)
            s += proj[(size_t)co*C_ + h*32 + cc] * attn[cc][d];
        g_weff[((size_t)b*C_ + co)*C_ + h*32 + d] = s;
    }
}

// ------------------ launcher ------------------
extern "C" void kernel_launch(void* const* d_in, const int* in_sizes, int n_in,
                              void* d_out, int out_size)
{
    const float* x           = (const float*)d_in[0];
    const float* y           = (const float*)d_in[1];
    const float* q_w         = (const float*)d_in[2];
    const float* kv_w        = (const float*)d_in[3];
    const float* kvdw_w      = (const float*)d_in[4];
    const float* proj_w      = (const float*)d_in[5];
    const float* temperature = (const float*)d_in[6];

    float *p_vraw, *p_vd;
    __half *p_xh,*p_yh,*p_yl,*p_vh,*p_vl,*p_kraw,*p_kd,*p_q16;
    __half *p_kvwh,*p_kvwl,*p_qwh,*p_wfh,*p_wfl;
    cudaGetSymbolAddress((void**)&p_vraw, g_vraw); cudaGetSymbolAddress((void**)&p_vd, g_vd);
    cudaGetSymbolAddress((void**)&p_kraw, g_kraw); cudaGetSymbolAddress((void**)&p_kd, g_kd);
    cudaGetSymbolAddress((void**)&p_q16, g_q16);
    cudaGetSymbolAddress((void**)&p_xh, g_xh);
    cudaGetSymbolAddress((void**)&p_yh, g_yh);   cudaGetSymbolAddress((void**)&p_yl, g_yl);
    cudaGetSymbolAddress((void**)&p_vh, g_vh);   cudaGetSymbolAddress((void**)&p_vl, g_vl);
    cudaGetSymbolAddress((void**)&p_kvwh, g_kvwh); cudaGetSymbolAddress((void**)&p_kvwl, g_kvwl);
    cudaGetSymbolAddress((void**)&p_qwh, g_qwh);
    cudaGetSymbolAddress((void**)&p_wfh, g_wfh); cudaGetSymbolAddress((void**)&p_wfl, g_wfl);

    const int SM_T1 = 98304;    // 2 stages x (24576 A + 24576 B)
    const int SM_T3 = 196608;   // 2 stages x (49152 A + 49152 B)
    cudaFuncSetAttribute(hgemm<9,1,1>, cudaFuncAttributeMaxDynamicSharedMemorySize, SM_T1);
    cudaFuncSetAttribute(hgemm<1,1,1>, cudaFuncAttributeMaxDynamicSharedMemorySize, SM_T1);
    cudaFuncSetAttribute(hgemm<1,3,0>, cudaFuncAttributeMaxDynamicSharedMemorySize, SM_T3);

    dim3 tb(32,8);
    // prepack
    pack_kvw<<<(384*192+255)/256, 256>>>(kv_w, p_kvwh, p_kvwl);
    pack_qw <<<(192*9*192+255)/256, 256>>>(q_w, p_qwh);
    t32pad<<<dim3(HW_/32, C_/32, B_), tb>>>(x, p_xh);
    zb<<<(B_*772*C_+255)/256, 256>>>(p_xh);
    t32<<<dim3(HW_/32, C_/32, B_), tb>>>(y, (size_t)C_*HW_, p_yh, p_yl);

    // k = kv_w[0:192] @ y   (1-term, fp16 out — attenuated path)
    hgemm<1,1,1><<<dim3(HW_/NT, B_), 384, SM_T1>>>(
        p_kvwh, nullptr, 0, p_yh, nullptr, (size_t)HW_*C_, (size_t)NT*C_,
        p_kraw, (size_t)C_*HW_);

    // v = kv_w[192:384] @ y (3-term, fp32 out — output linear in v)
    hgemm<1,3,0><<<dim3(HW_/NT, B_), 384, SM_T3>>>(
        p_kvwh + (size_t)192*192, p_kvwl + (size_t)192*192, 0,
        p_yh, p_yl, (size_t)HW_*C_, (size_t)NT*C_,
        p_vraw, (size_t)C_*HW_);

    // depthwise 3x3 (k fp16, v fp32)
    dwconv_t<__half><<<dim3(H_/32, C_, B_), 256>>>(p_kraw, kvdw_w, p_kd);
    dwconv_t<float ><<<dim3(H_/32, C_, B_), 256>>>(p_vraw, kvdw_w + 192*9, p_vd);

    // q = conv3x3(x) via 9 shifted GEMMs (1-term, fp16 out)
    hgemm<9,1,1><<<dim3(H_, B_), 384, SM_T1>>>(
        p_qwh, nullptr, 0, p_xh, nullptr, (size_t)PW*PW*C_, (size_t)PW*C_,
        p_q16, (size_t)C_*HW_);

    // v -> pixel-major fp16 hi/lo
    t32<<<dim3(HW_/32, C_/32, B_), tb>>>(p_vd, (size_t)C_*HW_, p_vh, p_vl);

    // gram (+fused norms), softmax, fold proj
    zero_acc<<<(B_*HEADS*32*32 + 2*B_*C_ + 255)/256, 256>>>();
    gram_kernel<<<dim3(8, B_*HEADS), 256>>>(p_q16, p_kd);
    softfold<<<B_*HEADS, 256>>>(temperature, proj_w);
    pack_weff<<<(B_*192*192+255)/256, 256>>>(p_wfh, p_wfl);

    // out = W_eff[b](192x192) @ v[b]  (3-term, fp32 out)
    hgemm<1,3,0><<<dim3(HW_/NT, B_), 384, SM_T3>>>(
        p_wfh, p_wfl, (size_t)192*192, p_vh, p_vl, (size_t)HW_*C_, (size_t)NT*C_,
        d_out, (size_t)C_*HW_);
}